// round 1
// baseline (speedup 1.0000x reference)
#include <cuda_runtime.h>

// MultiScaleMovingAvg: out[b,s,f] = sum_i softmax(kw)[i] * boxavg_{k_i}(x[b,:,f])[s]
// k in {3,7,15,31}, replicate padding along S.
// Strategy: per-thread column sliding-window running sums, 64-entry register
// rolling buffer with static indexing (unroll 64), 33-step load prefetch distance.

#define B_DIM 16
#define S_DIM 4096
#define F_DIM 512
#define SEG   512
#define TPB   128

__global__ __launch_bounds__(TPB, 1)
void msma_kernel(const float* __restrict__ x,
                 const float* __restrict__ kw,
                 float* __restrict__ out) {
    const int f  = blockIdx.x * TPB + threadIdx.x;   // 0..511
    const int s0 = blockIdx.y * SEG;                 // multiple of 64
    const int b  = blockIdx.z;

    // softmax over the 4 kernel weights, folded with 1/k
    const float k0 = kw[0], k1 = kw[1], k2 = kw[2], k3 = kw[3];
    const float m  = fmaxf(fmaxf(k0, k1), fmaxf(k2, k3));
    const float e0 = __expf(k0 - m), e1 = __expf(k1 - m);
    const float e2 = __expf(k2 - m), e3 = __expf(k3 - m);
    const float inv = 1.0f / (e0 + e1 + e2 + e3);
    const float c3  = e0 * inv * (1.0f / 3.0f);
    const float c7  = e1 * inv * (1.0f / 7.0f);
    const float c15 = e2 * inv * (1.0f / 15.0f);
    const float c31 = e3 * inv * (1.0f / 31.0f);

    const float* __restrict__ xc = x   + ((size_t)b * S_DIM) * F_DIM + f;
    float* __restrict__       oc = out + ((size_t)b * S_DIM + s0) * F_DIM + f;

    // Rolling buffer: slot j&63 holds x[clamp(j)] for j in [s-15, s+48]
    float R[64];

    // Prologue: fill j in [s0-15, s0+48]  (both clamps; s0 is mult of 64 so slot=(t+64)&63)
    #pragma unroll
    for (int t = -15; t <= 48; ++t) {
        int j = s0 + t;
        j = j < 0 ? 0 : j;
        j = j > (S_DIM - 1) ? (S_DIM - 1) : j;
        R[(t + 64) & 63] = xc[(size_t)j * F_DIM];
    }

    // Initial window sums at s = s0 (hierarchical)
    float W3 = R[63] + R[0] + R[1];
    float W7 = W3;
    #pragma unroll
    for (int t = 2; t <= 3; ++t)  W7  += R[t & 63] + R[(64 - t) & 63];
    float W15 = W7;
    #pragma unroll
    for (int t = 4; t <= 7; ++t)  W15 += R[t & 63] + R[(64 - t) & 63];
    float W31 = W15;
    #pragma unroll
    for (int t = 8; t <= 15; ++t) W31 += R[t & 63] + R[(64 - t) & 63];

    if (s0 + SEG + 48 <= S_DIM - 1) {
        // FAST PATH: no load ever needs clamping (j_max = s0+SEG+48 <= S-1).
        // Pure pointer + immediate-offset addressing.
        const float* __restrict__ lp = xc + (size_t)(s0 + 49) * F_DIM;
        float* __restrict__       op = oc;
        for (int sb = 0; sb < SEG; sb += 64) {
            #pragma unroll
            for (int u = 0; u < 64; ++u) {
                float o = c3 * W3;
                o = fmaf(c7,  W7,  o);
                o = fmaf(c15, W15, o);
                o = fmaf(c31, W31, o);
                op[(size_t)u * F_DIM] = o;
                W3  += R[(u + 2)  & 63] - R[(u + 63) & 63];
                W7  += R[(u + 4)  & 63] - R[(u + 61) & 63];
                W15 += R[(u + 8)  & 63] - R[(u + 57) & 63];
                W31 += R[(u + 16) & 63] - R[(u + 49) & 63];
                // refill the slot just vacated by x[s-15]; consumed 33 steps later
                R[(u + 49) & 63] = lp[(size_t)u * F_DIM];
            }
            lp += (size_t)64 * F_DIM;
            op += (size_t)64 * F_DIM;
        }
    } else {
        // SLOW PATH (last segment of each column): clamp load index to S-1.
        float* __restrict__ op = oc;
        for (int sb = 0; sb < SEG; sb += 64) {
            #pragma unroll
            for (int u = 0; u < 64; ++u) {
                float o = c3 * W3;
                o = fmaf(c7,  W7,  o);
                o = fmaf(c15, W15, o);
                o = fmaf(c31, W31, o);
                op[(size_t)u * F_DIM] = o;
                W3  += R[(u + 2)  & 63] - R[(u + 63) & 63];
                W7  += R[(u + 4)  & 63] - R[(u + 61) & 63];
                W15 += R[(u + 8)  & 63] - R[(u + 57) & 63];
                W31 += R[(u + 16) & 63] - R[(u + 49) & 63];
                int j = s0 + sb + u + 49;           // >= 49, only upper clamp needed
                j = j > (S_DIM - 1) ? (S_DIM - 1) : j;
                R[(u + 49) & 63] = xc[(size_t)j * F_DIM];
            }
            op += (size_t)64 * F_DIM;
        }
    }
}

extern "C" void kernel_launch(void* const* d_in, const int* in_sizes, int n_in,
                              void* d_out, int out_size) {
    const float* x  = (const float*)d_in[0];   // [16, 4096, 512] fp32
    const float* kw = (const float*)d_in[1];   // [4] fp32
    float* out = (float*)d_out;                // [16, 4096, 512] fp32

    dim3 grid(F_DIM / TPB, S_DIM / SEG, B_DIM); // (4, 8, 16) = 512 blocks
    msma_kernel<<<grid, TPB>>>(x, kw, out);
}

// round 2
// speedup vs baseline: 1.1489x; 1.1489x over previous
#include <cuda_runtime.h>

// MultiScaleMovingAvg: out[b,s,f] = sum_i softmax(kw)[i] * boxavg_{k_i}(x[b,:,f])[s]
// k in {3,7,15,31}, replicate padding along S.
// R2: 32-slot rolling window + 8-deep prefetch queue (low regs -> 7 CTAs/SM),
// SEG=256 -> 4096 warps in a single wave. TLP is the latency-hiding lever.

#define B_DIM 16
#define S_DIM 4096
#define F_DIM 512
#define SEG   256
#define TPB   128

__global__ __launch_bounds__(TPB, 7)
void msma_kernel(const float* __restrict__ x,
                 const float* __restrict__ kw,
                 float* __restrict__ out) {
    const int f  = blockIdx.x * TPB + threadIdx.x;   // 0..511
    const int s0 = blockIdx.y * SEG;                 // multiple of 256
    const int b  = blockIdx.z;

    // softmax over the 4 kernel weights, folded with 1/k
    const float k0 = kw[0], k1 = kw[1], k2 = kw[2], k3 = kw[3];
    const float m  = fmaxf(fmaxf(k0, k1), fmaxf(k2, k3));
    const float e0 = __expf(k0 - m), e1 = __expf(k1 - m);
    const float e2 = __expf(k2 - m), e3 = __expf(k3 - m);
    const float inv = 1.0f / (e0 + e1 + e2 + e3);
    const float c3  = e0 * inv * (1.0f / 3.0f);
    const float c7  = e1 * inv * (1.0f / 7.0f);
    const float c15 = e2 * inv * (1.0f / 15.0f);
    const float c31 = e3 * inv * (1.0f / 31.0f);

    const float* __restrict__ xc = x   + ((size_t)b * S_DIM) * F_DIM + f;
    float* __restrict__       op = out + ((size_t)b * S_DIM + s0) * F_DIM + f;

    // R[j & 31] holds x[clamp(j)] for the current window j in [s-15, s+16].
    // Pf[u & 7] holds the in-flight load x[s+17+ (queue pos)] -> 8-step distance.
    float R[32];
    float Pf[8];

    // Prologue: window [s0-15, s0+16]. Max index s0+32 <= 3872 < 4096, so
    // only the lower clamp is ever needed.
    #pragma unroll
    for (int t = -15; t <= 16; ++t) {
        int j = s0 + t;
        j = j < 0 ? 0 : j;
        R[(t + 32) & 31] = xc[(size_t)j * F_DIM];
    }
    #pragma unroll
    for (int i = 0; i < 8; ++i) {
        Pf[i] = xc[(size_t)(s0 + 17 + i) * F_DIM];   // x[s0+17 .. s0+24], never OOB
    }

    // Initial window sums at s = s0 (s0 & 31 == 0)
    float W3 = R[31] + R[0] + R[1];
    float W7 = W3;
    #pragma unroll
    for (int t = 2; t <= 3; ++t)  W7  += R[t] + R[(32 - t) & 31];
    float W15 = W7;
    #pragma unroll
    for (int t = 4; t <= 7; ++t)  W15 += R[t] + R[(32 - t) & 31];
    float W31 = W15;
    #pragma unroll
    for (int t = 8; t <= 15; ++t) W31 += R[t] + R[(32 - t) & 31];

    if (s0 + SEG - 1 + 25 <= S_DIM - 1) {
        // FAST PATH: no load in the main loop needs clamping.
        const float* __restrict__ lp = xc + (size_t)(s0 + 25) * F_DIM;
        for (int sb = 0; sb < SEG; sb += 32) {
            #pragma unroll
            for (int u = 0; u < 32; ++u) {
                float o = c3 * W3;
                o = fmaf(c7,  W7,  o);
                o = fmaf(c15, W15, o);
                o = fmaf(c31, W31, o);
                op[(size_t)u * F_DIM] = o;
                W3  += R[(u + 2)  & 31] - R[(u + 31) & 31];  // +x[s+2]  -x[s-1]
                W7  += R[(u + 4)  & 31] - R[(u + 29) & 31];  // +x[s+4]  -x[s-3]
                W15 += R[(u + 8)  & 31] - R[(u + 25) & 31];  // +x[s+8]  -x[s-7]
                W31 += R[(u + 16) & 31] - R[(u + 17) & 31];  // +x[s+16] -x[s-15]
                R[(u + 17) & 31] = Pf[u & 7];                // insert x[s+17]
                Pf[u & 7] = lp[(size_t)u * F_DIM];           // load x[s+25]
            }
            lp += (size_t)32 * F_DIM;
            op += (size_t)32 * F_DIM;
        }
    } else {
        // SLOW PATH (last S-segment only): clamp load index to S-1.
        for (int sb = 0; sb < SEG; sb += 32) {
            #pragma unroll
            for (int u = 0; u < 32; ++u) {
                float o = c3 * W3;
                o = fmaf(c7,  W7,  o);
                o = fmaf(c15, W15, o);
                o = fmaf(c31, W31, o);
                op[(size_t)u * F_DIM] = o;
                W3  += R[(u + 2)  & 31] - R[(u + 31) & 31];
                W7  += R[(u + 4)  & 31] - R[(u + 29) & 31];
                W15 += R[(u + 8)  & 31] - R[(u + 25) & 31];
                W31 += R[(u + 16) & 31] - R[(u + 17) & 31];
                R[(u + 17) & 31] = Pf[u & 7];
                int j = s0 + sb + u + 25;                    // >= 25, upper clamp only
                j = j > (S_DIM - 1) ? (S_DIM - 1) : j;
                Pf[u & 7] = xc[(size_t)j * F_DIM];
            }
            op += (size_t)32 * F_DIM;
        }
    }
}

extern "C" void kernel_launch(void* const* d_in, const int* in_sizes, int n_in,
                              void* d_out, int out_size) {
    const float* x  = (const float*)d_in[0];   // [16, 4096, 512] fp32
    const float* kw = (const float*)d_in[1];   // [4] fp32
    float* out = (float*)d_out;                // [16, 4096, 512] fp32

    dim3 grid(F_DIM / TPB, S_DIM / SEG, B_DIM); // (4, 16, 16) = 1024 blocks
    msma_kernel<<<grid, TPB>>>(x, kw, out);
}

// round 4
// speedup vs baseline: 1.1553x; 1.0056x over previous
#include <cuda_runtime.h>

// MultiScaleMovingAvg via per-thread running box sums.
// R4: warp-autonomous cp.async pipeline into per-warp smem ring (precise
// wait_group ordering -> real MLP), 16-entry register window for short taps,
// 3 LDS/step for long taps + refill. No __syncthreads in the hot loop.
// Fix vs R3: full drain (wait_group 0) at i = SEG/16-2 so the final two
// groups land before the last iteration reads them.

#define B_DIM 16
#define S_DIM 4096
#define F_DIM 512
#define SEG   256
#define TPB   128
#define RING  64          // rows per warp ring (power of 2)

__device__ __forceinline__ void cp_async16(unsigned saddr, const void* gptr) {
    asm volatile("cp.async.cg.shared.global [%0], [%1], 16;\n"
                 :: "r"(saddr), "l"(gptr));
}
__device__ __forceinline__ void cp_commit() {
    asm volatile("cp.async.commit_group;\n");
}
template <int N>
__device__ __forceinline__ void cp_wait() {
    asm volatile("cp.async.wait_group %0;\n" :: "n"(N));
}

__global__ void __launch_bounds__(TPB)
msma_kernel(const float* __restrict__ x,
            const float* __restrict__ kw,
            float* __restrict__ out) {
    __shared__ float ring[4][RING][32];   // 32 KB

    const int lane = threadIdx.x & 31;
    const int warp = threadIdx.x >> 5;
    const int f0   = blockIdx.x * TPB + warp * 32;  // 32 channels per warp
    const int s0   = blockIdx.y * SEG;              // multiple of 256
    const int b    = blockIdx.z;

    // softmax over the 4 kernel weights, folded with 1/k
    const float k0 = kw[0], k1 = kw[1], k2 = kw[2], k3 = kw[3];
    const float mx = fmaxf(fmaxf(k0, k1), fmaxf(k2, k3));
    const float e0 = __expf(k0 - mx), e1 = __expf(k1 - mx);
    const float e2 = __expf(k2 - mx), e3 = __expf(k3 - mx);
    const float inv = 1.0f / (e0 + e1 + e2 + e3);
    const float c3  = e0 * inv * (1.0f / 3.0f);
    const float c7  = e1 * inv * (1.0f / 7.0f);
    const float c15 = e2 * inv * (1.0f / 15.0f);
    const float c31 = e3 * inv * (1.0f / 31.0f);

    const float* __restrict__ xb = x + (size_t)b * S_DIM * F_DIM;
    float (* __restrict__ rw)[32] = ring[warp];

    // producer mapping: one cp.async round of 8 lanes = one 128B row
    const int prow  = lane >> 3;          // 0..3 (row within quad)
    const int pcol  = (lane & 7) << 2;    // channel offset 0,4,..,28
    const unsigned rbase =
        (unsigned)__cvta_generic_to_shared(&ring[warp][0][0]);
    const unsigned pbyte = (unsigned)(pcol << 2); // 16B per lane

    // issue one 8-row group [r, r+7] (rows clamped to [0, S-1]); slot = row & 63
    auto issue_group = [&](int r) {
        int ra = r + prow, rb = r + 4 + prow;
        int ca = ra < 0 ? 0 : (ra > S_DIM - 1 ? S_DIM - 1 : ra);
        int cb = rb < 0 ? 0 : (rb > S_DIM - 1 ? S_DIM - 1 : rb);
        unsigned da = rbase + ((unsigned)(ra & (RING - 1)) << 7) + pbyte;
        unsigned db = rbase + ((unsigned)(rb & (RING - 1)) << 7) + pbyte;
        cp_async16(da, xb + (size_t)ca * F_DIM + f0 + pcol);
        cp_async16(db, xb + (size_t)cb * F_DIM + f0 + pcol);
        cp_commit();
    };

    // ---- Prologue: stage rows [s0-16, s0+47] (8 groups), keep 2 in flight ----
    #pragma unroll
    for (int g = 0; g < 8; ++g) issue_group(s0 - 16 + 8 * g);
    cp_wait<2>();            // rows [s0-16, s0+31] complete
    __syncwarp();

    // Build initial window sums at s = s0 and register ring Q[s0-7 .. s0+8].
    // s0 % 64 == 0, so slot(s0+t) = t & 63 (compile-time).
    float W3 = 0.f, W7 = 0.f, W15 = 0.f, W31 = 0.f;
    float Q[16];
    #pragma unroll
    for (int t = -15; t <= 16; ++t) {
        float v = rw[t & (RING - 1)][lane];
        if (t >= -15 && t <= 15) W31 += v;
        if (t >= -7  && t <= 7 ) W15 += v;
        if (t >= -3  && t <= 3 ) W7  += v;
        if (t >= -1  && t <= 1 ) W3  += v;
        if (t >= -7  && t <= 8 ) Q[t & 15] = v;
    }

    float* __restrict__ op = out + ((size_t)b * S_DIM + s0) * F_DIM + f0 + lane;

    // ---- Main loop: 16 outputs per iteration ----
    // Invariant at top (first output rel-row t): rows <= t+31 complete,
    // rows (t+31, t+47] pending (2 groups).
    #pragma unroll 1
    for (int i = 0; i < SEG / 16; ++i) {
        const int t = i * 16;
        #pragma unroll
        for (int u = 0; u < 16; ++u) {
            float o = c3 * W3;
            o = fmaf(c7,  W7,  o);
            o = fmaf(c15, W15, o);
            o = fmaf(c31, W31, o);
            op[(size_t)u * F_DIM] = o;
            const int s = t + u;                    // rel row; slot = (s+C) & 63
            float xp16 = rw[(s + 16) & (RING - 1)][lane];
            float xm15 = rw[(s - 15) & (RING - 1)][lane];
            float xp9  = rw[(s + 9)  & (RING - 1)][lane];
            W3  += Q[(u + 2)  & 15] - Q[(u + 15) & 15];  // +x[s+2]  -x[s-1]
            W7  += Q[(u + 4)  & 15] - Q[(u + 13) & 15];  // +x[s+4]  -x[s-3]
            W15 += Q[(u + 8)  & 15] - Q[(u + 9)  & 15];  // +x[s+8]  -x[s-7]
            W31 += xp16 - xm15;                          // +x[s+16] -x[s-15]
            Q[(u + 9) & 15] = xp9;                       // insert x[s+9]
        }
        op += (size_t)16 * F_DIM;
        // stage rows [t+48, t+63] (only while any row <= SEG+15 is needed)
        if (t + 48 <= SEG + 15) issue_group(s0 + t + 48);
        if (t + 56 <= SEG + 15) issue_group(s0 + t + 56);
        // Tail fix: at i = SEG/16-2 nothing new was issued but the final two
        // groups (rows [SEG, SEG+15]) are still pending; drain them fully so
        // the last iteration's xp16 reads (up to row SEG+15) are valid.
        if (i == SEG / 16 - 2) cp_wait<0>(); else cp_wait<2>();
        __syncwarp();
    }
}

extern "C" void kernel_launch(void* const* d_in, const int* in_sizes, int n_in,
                              void* d_out, int out_size) {
    const float* x  = (const float*)d_in[0];   // [16, 4096, 512] fp32
    const float* kw = (const float*)d_in[1];   // [4] fp32
    float* out = (float*)d_out;                // [16, 4096, 512] fp32

    dim3 grid(F_DIM / TPB, S_DIM / SEG, B_DIM); // (4, 16, 16) = 1024 blocks
    msma_kernel<<<grid, TPB>>>(x, kw, out);
}

// round 5
// speedup vs baseline: 1.1676x; 1.0106x over previous
#include <cuda_runtime.h>

// MultiScaleMovingAvg via per-thread running box sums.
// R5: 32-entry register window Q serves ALL taps (1 LDS/step, just the
// x[s+17] insert). Per-warp smem ring shrinks to 32 rows (4KB/warp,
// 16KB/CTA) -> single wave, grid-limited occupancy. cp.async pipeline
// keeps 2 groups (16 rows) in flight; full drain at first non-issuing
// half-block. No __syncthreads anywhere.

#define B_DIM 16
#define S_DIM 4096
#define F_DIM 512
#define SEG   256
#define TPB   128
#define RING  32          // rows per warp ring (power of 2)

__device__ __forceinline__ void cp_async16(unsigned saddr, const void* gptr) {
    asm volatile("cp.async.cg.shared.global [%0], [%1], 16;\n"
                 :: "r"(saddr), "l"(gptr));
}
__device__ __forceinline__ void cp_commit() {
    asm volatile("cp.async.commit_group;\n");
}
template <int N>
__device__ __forceinline__ void cp_wait() {
    asm volatile("cp.async.wait_group %0;\n" :: "n"(N));
}

__global__ void __launch_bounds__(TPB)
msma_kernel(const float* __restrict__ x,
            const float* __restrict__ kw,
            float* __restrict__ out) {
    __shared__ float ring[4][RING][32];   // 16 KB

    const int lane = threadIdx.x & 31;
    const int warp = threadIdx.x >> 5;
    const int f0   = blockIdx.x * TPB + warp * 32;  // 32 channels per warp
    const int s0   = blockIdx.y * SEG;              // multiple of 256
    const int b    = blockIdx.z;

    // softmax over the 4 kernel weights, folded with 1/k
    const float k0 = kw[0], k1 = kw[1], k2 = kw[2], k3 = kw[3];
    const float mx = fmaxf(fmaxf(k0, k1), fmaxf(k2, k3));
    const float e0 = __expf(k0 - mx), e1 = __expf(k1 - mx);
    const float e2 = __expf(k2 - mx), e3 = __expf(k3 - mx);
    const float inv = 1.0f / (e0 + e1 + e2 + e3);
    const float c3  = e0 * inv * (1.0f / 3.0f);
    const float c7  = e1 * inv * (1.0f / 7.0f);
    const float c15 = e2 * inv * (1.0f / 15.0f);
    const float c31 = e3 * inv * (1.0f / 31.0f);

    const float* __restrict__ xb = x + (size_t)b * S_DIM * F_DIM;
    float (* __restrict__ rw)[32] = ring[warp];

    // producer mapping: one cp.async round of 8 lanes = one 128B row
    const int prow = lane >> 3;           // 0..3 (row within quad)
    const int pcol = (lane & 7) << 2;     // channel offset 0,4,..,28
    const unsigned rbase =
        (unsigned)__cvta_generic_to_shared(&ring[warp][0][0]);
    const unsigned pbyte = (unsigned)(pcol << 2);

    // issue one 8-row group [r, r+7]; slot keyed by LOGICAL row & 31,
    // data from row clamped to [0, S-1]  (replicate padding)
    auto issue_group = [&](int r) {
        int ra = r + prow, rb = r + 4 + prow;
        int ca = ra < 0 ? 0 : (ra > S_DIM - 1 ? S_DIM - 1 : ra);
        int cb = rb < 0 ? 0 : (rb > S_DIM - 1 ? S_DIM - 1 : rb);
        unsigned da = rbase + ((unsigned)(ra & (RING - 1)) << 7) + pbyte;
        unsigned db = rbase + ((unsigned)(rb & (RING - 1)) << 7) + pbyte;
        cp_async16(da, xb + (size_t)ca * F_DIM + f0 + pcol);
        cp_async16(db, xb + (size_t)cb * F_DIM + f0 + pcol);
        cp_commit();
    };

    // ---- Prologue phase 1: rows [s0-15, s0+16] fill the whole ring ----
    issue_group(s0 - 15); issue_group(s0 - 7);
    issue_group(s0 + 1);  issue_group(s0 + 9);
    cp_wait<0>();
    __syncwarp();

    // Q[row & 31] = x[row] for rows s0-15 .. s0+16  (s0 % 32 == 0)
    float Q[32];
    #pragma unroll
    for (int i = 0; i < 32; ++i) Q[i] = rw[i][lane];

    // initial window sums at s = s0 (slot of s0+t is t & 31)
    float W3 = Q[31] + Q[0] + Q[1];
    float W7 = W3;
    #pragma unroll
    for (int t = 2; t <= 3; ++t)  W7  += Q[t] + Q[32 - t];
    float W15 = W7;
    #pragma unroll
    for (int t = 4; t <= 7; ++t)  W15 += Q[t] + Q[32 - t];
    float W31 = W15;
    #pragma unroll
    for (int t = 8; t <= 15; ++t) W31 += Q[t] + Q[32 - t];

    __syncwarp();   // all lanes done reading ring before slots get reused

    // ---- Prologue phase 2: rows [s0+17, s0+48]; keep 2 groups pending ----
    issue_group(s0 + 17); issue_group(s0 + 25);
    issue_group(s0 + 33); issue_group(s0 + 41);
    cp_wait<2>();            // rows <= s0+32 complete; (s0+32, s0+48] pending
    __syncwarp();

    float* __restrict__ op = out + ((size_t)b * S_DIM + s0) * F_DIM + f0 + lane;

    // ---- Main loop: outer blocks of 32 steps = 2 half-blocks of 16 ----
    // Invariant at top of half-block p: rows <= p+32 complete,
    // (p+32, p+48] pending (2 groups).
    #pragma unroll 1
    for (int ob = 0; ob < SEG / 32; ++ob) {
        #pragma unroll
        for (int h = 0; h < 2; ++h) {
            const int PAR = h * 16;                  // compile-time after unroll
            #pragma unroll
            for (int u = 0; u < 16; ++u) {
                const int sl = PAR + u;              // compile-time
                float o = c3 * W3;
                o = fmaf(c7,  W7,  o);
                o = fmaf(c15, W15, o);
                o = fmaf(c31, W31, o);
                op[(size_t)sl * F_DIM] = o;
                W3  += Q[(sl + 2)  & 31] - Q[(sl + 31) & 31]; // +x[s+2]  -x[s-1]
                W7  += Q[(sl + 4)  & 31] - Q[(sl + 29) & 31]; // +x[s+4]  -x[s-3]
                W15 += Q[(sl + 8)  & 31] - Q[(sl + 25) & 31]; // +x[s+8]  -x[s-7]
                W31 += Q[(sl + 16) & 31] - Q[(sl + 17) & 31]; // +x[s+16] -x[s-15]
                Q[(sl + 17) & 31] = rw[(sl + 17) & 31][lane]; // insert x[s+17]
            }
            const int p_rel = ob * 32 + PAR;
            if (p_rel + 49 <= SEG + 16) {
                // stage rows [p+49, p+64]
                issue_group(s0 + p_rel + 49);
                issue_group(s0 + p_rel + 57);
                cp_wait<2>();
            } else if (p_rel == SEG - 32) {
                cp_wait<0>();   // drain final pending groups (rows <= SEG+16)
            }
            __syncwarp();
        }
        op += (size_t)32 * F_DIM;
    }
}

extern "C" void kernel_launch(void* const* d_in, const int* in_sizes, int n_in,
                              void* d_out, int out_size) {
    const float* x  = (const float*)d_in[0];   // [16, 4096, 512] fp32
    const float* kw = (const float*)d_in[1];   // [4] fp32
    float* out = (float*)d_out;                // [16, 4096, 512] fp32

    dim3 grid(F_DIM / TPB, S_DIM / SEG, B_DIM); // (4, 16, 16) = 1024 blocks
    msma_kernel<<<grid, TPB>>>(x, kw, out);
}